// round 13
// baseline (speedup 1.0000x reference)
#include <cuda_runtime.h>

#define FULL 0xFFFFFFFFu
typedef unsigned long long u64;

constexpr int B = 2048;
constexpr int T = 4096;
constexpr int CH = 8;              // steps per chunk
constexpr int NCHUNK = T / CH;     // 512

__device__ __forceinline__ float tanhf_a(float x){ float y; asm("tanh.approx.f32 %0,%1;":"=f"(y):"f"(x)); return y; }
__device__ __forceinline__ u64 ffma2(u64 a, u64 b, u64 c){
    u64 d; asm("fma.rn.f32x2 %0,%1,%2,%3;" : "=l"(d) : "l"(a), "l"(b), "l"(c)); return d;
}
__device__ __forceinline__ u64 fmul2(u64 a, u64 b){
    u64 d; asm("mul.rn.f32x2 %0,%1,%2;" : "=l"(d) : "l"(a), "l"(b)); return d;
}
__device__ __forceinline__ u64 fadd2(u64 a, u64 b){
    u64 d; asm("add.rn.f32x2 %0,%1,%2;" : "=l"(d) : "l"(a), "l"(b)); return d;
}
__device__ __forceinline__ u64 pack2(float lo, float hi){
    u64 d; asm("mov.b64 %0,{%1,%2};" : "=l"(d) : "f"(lo), "f"(hi)); return d;
}
__device__ __forceinline__ void unpack2(u64 v, float& lo, float& hi){
    asm("mov.b64 {%0,%1},%2;" : "=f"(lo), "=f"(hi) : "l"(v));
}
__device__ __forceinline__ u64 dup2(float v){ return pack2(v, v); }

// TWO independent 4-batch streams per warp, compiler-interleaved.
// Per stream: lane = (group = lane>>3, unit u = lane&7); lane computes all
// 4 gates of its unit, pair-packed (i,f),(g,o) in f32x2 (weights shared
// between streams). The streams have no cross-dependencies, so their
// ~95-cycle recurrence chains mutually hide under the warp's issue stream.
// No shared memory, no barriers.
// Activations via MUFU.TANH: sigmoid(z)=0.5*tanh(0.5z)+0.5, 0.5 pre-folded.
__global__ void __launch_bounds__(64, 1)
lstm2_kernel(const float* __restrict__ x,
             const float* __restrict__ Wih0, const float* __restrict__ Whh0,
             const float* __restrict__ bih0, const float* __restrict__ bhh0,
             const float* __restrict__ Wih1, const float* __restrict__ Whh1,
             const float* __restrict__ bih1, const float* __restrict__ bhh1,
             const float* __restrict__ Wlin, const float* __restrict__ blin,
             float* __restrict__ out)
{
    const int lane  = threadIdx.x & 31;
    const int gwarp = blockIdx.x * 2 + (threadIdx.x >> 5);  // 0..255
    const int u     = lane & 7;
    const int grp   = lane >> 3;
    const int base  = lane & 24;

    const float Hs = 0.5f;

    // ---- shared weights: pre-scaled, pair-packed ----
    u64 whh0_if[8], whh0_go[8], wih1_if[8], wih1_go[8], whh1_if[8], whh1_go[8];
#pragma unroll
    for (int k = 0; k < 8; k++) {
        whh0_if[k] = pack2(Hs*Whh0[u*8+k],      Hs*Whh0[(8+u)*8+k]);
        whh0_go[k] = pack2(Whh0[(16+u)*8+k],    Hs*Whh0[(24+u)*8+k]);
        wih1_if[k] = pack2(Hs*Wih1[u*8+k],      Hs*Wih1[(8+u)*8+k]);
        wih1_go[k] = pack2(Wih1[(16+u)*8+k],    Hs*Wih1[(24+u)*8+k]);
        whh1_if[k] = pack2(Hs*Whh1[u*8+k],      Hs*Whh1[(8+u)*8+k]);
        whh1_go[k] = pack2(Whh1[(16+u)*8+k],    Hs*Whh1[(24+u)*8+k]);
    }
    const u64 wx_if0 = pack2(Hs*Wih0[u],    Hs*Wih0[8+u]);
    const u64 wx_go0 = pack2(Wih0[16+u],    Hs*Wih0[24+u]);
    const u64 b_if0  = pack2(Hs*(bih0[u]+bhh0[u]),      Hs*(bih0[8+u]+bhh0[8+u]));
    const u64 b_go0  = pack2((bih0[16+u]+bhh0[16+u]),   Hs*(bih0[24+u]+bhh0[24+u]));
    const u64 b_if1  = pack2(Hs*(bih1[u]+bhh1[u]),      Hs*(bih1[8+u]+bhh1[8+u]));
    const u64 b_go1  = pack2((bih1[16+u]+bhh1[16+u]),   Hs*(bih1[24+u]+bhh1[24+u]));
    const float wlu = Wlin[u];
    const float blv = blin[0];

    // ---- per-stream state ----
    u64 h1x[2][8], h2x[2][8];
    float c1[2] = {0.f, 0.f}, c2[2] = {0.f, 0.f}, pbuf[2] = {0.f, 0.f};
#pragma unroll
    for (int s = 0; s < 2; s++)
#pragma unroll
        for (int k = 0; k < 8; k++) { h1x[s][k] = 0ull; h2x[s][k] = 0ull; }

    const float* xrow[2];
    float* ob[2];
    float xcur[2], xnext[2];
#pragma unroll
    for (int s = 0; s < 2; s++) {
        const int b = gwarp * 8 + s * 4 + grp;      // this lane's batch, stream s
        xrow[s] = x   + (size_t)b * T + u;           // lane holds x[b][c*CH + u]
        ob[s]   = out + (size_t)b * T;
        xcur[s] = xrow[s][0];
    }

    // L0: consumes x[t+1] + h1x[s] (= h1[t]), produces h1x[s] = h1[t+1], c1[s].
    auto L0 = [&](int s, float xt) {
        u64 xd   = dup2(xt);
        u64 aif0 = ffma2(wx_if0, xd, b_if0);
        u64 ago0 = ffma2(wx_go0, xd, b_go0);
        u64 aif1 = fmul2(whh0_if[4], h1x[s][4]);
        u64 ago1 = fmul2(whh0_go[4], h1x[s][4]);
#pragma unroll
        for (int k = 0; k < 4; k++) {
            aif0 = ffma2(whh0_if[k], h1x[s][k], aif0);
            ago0 = ffma2(whh0_go[k], h1x[s][k], ago0);
        }
#pragma unroll
        for (int k = 5; k < 8; k++) {
            aif1 = ffma2(whh0_if[k], h1x[s][k], aif1);
            ago1 = ffma2(whh0_go[k], h1x[s][k], ago1);
        }
        u64 aif = fadd2(aif0, aif1);
        u64 ago = fadd2(ago0, ago1);
        float zi, zf, zg, zo;
        unpack2(aif, zi, zf);
        unpack2(ago, zg, zo);
        float iv = fmaf(0.5f, tanhf_a(zi), 0.5f);
        float fv = fmaf(0.5f, tanhf_a(zf), 0.5f);
        float gv = tanhf_a(zg);
        float ov = fmaf(0.5f, tanhf_a(zo), 0.5f);
        c1[s] = fmaf(fv, c1[s], iv * gv);
        float h = ov * tanhf_a(c1[s]);
#pragma unroll
        for (int k = 0; k < 8; k++)
            h1x[s][k] = dup2(__shfl_sync(FULL, h, base + k));
    };

    // prologue: h1[0] for both streams
#pragma unroll
    for (int s = 0; s < 2; s++)
        L0(s, __shfl_sync(FULL, xcur[s], base));

    for (int c = 0; c < NCHUNK; c++) {
#pragma unroll
        for (int s = 0; s < 2; s++) {
            xnext[s] = 0.f;
            if (c + 1 < NCHUNK) xnext[s] = xrow[s][(c + 1) * CH];
        }

#pragma unroll
        for (int s8 = 0; s8 < CH; s8++) {
            // ---- section 1: L1-input matvec (Wih1*h1[t] + b1), both streams ----
            u64 mif0[2], mgo0[2], mif1[2], mgo1[2];
#pragma unroll
            for (int s = 0; s < 2; s++) {
                mif0[s] = ffma2(wih1_if[0], h1x[s][0], b_if1);
                mgo0[s] = ffma2(wih1_go[0], h1x[s][0], b_go1);
                mif1[s] = fmul2(wih1_if[4], h1x[s][4]);
                mgo1[s] = fmul2(wih1_go[4], h1x[s][4]);
#pragma unroll
                for (int k = 1; k < 4; k++) {
                    mif0[s] = ffma2(wih1_if[k], h1x[s][k], mif0[s]);
                    mgo0[s] = ffma2(wih1_go[k], h1x[s][k], mgo0[s]);
                }
#pragma unroll
                for (int k = 5; k < 8; k++) {
                    mif1[s] = ffma2(wih1_if[k], h1x[s][k], mif1[s]);
                    mgo1[s] = ffma2(wih1_go[k], h1x[s][k], mgo1[s]);
                }
            }

            // ---- section 2: L0 for x-step t+1, both streams (indep chains) ----
#pragma unroll
            for (int s = 0; s < 2; s++) {
                float xt = (s8 < 7) ? __shfl_sync(FULL, xcur[s], base + s8 + 1)
                                    : __shfl_sync(FULL, xnext[s], base);
                L0(s, xt);
                // last chunk's final step computes harmless garbage h1[T]
                // from zero-filled xnext (never read, no OOB)
            }

            // ---- section 3: L1 tail (Whh1*h2 + act + head + redist), both ----
#pragma unroll
            for (int s = 0; s < 2; s++) {
                u64 bif0 = ffma2(whh1_if[0], h2x[s][0], mif0[s]);
                u64 bgo0 = ffma2(whh1_go[0], h2x[s][0], mgo0[s]);
                u64 bif1 = ffma2(whh1_if[4], h2x[s][4], mif1[s]);
                u64 bgo1 = ffma2(whh1_go[4], h2x[s][4], mgo1[s]);
#pragma unroll
                for (int k = 1; k < 4; k++) {
                    bif0 = ffma2(whh1_if[k], h2x[s][k], bif0);
                    bgo0 = ffma2(whh1_go[k], h2x[s][k], bgo0);
                }
#pragma unroll
                for (int k = 5; k < 8; k++) {
                    bif1 = ffma2(whh1_if[k], h2x[s][k], bif1);
                    bgo1 = ffma2(whh1_go[k], h2x[s][k], bgo1);
                }
                u64 aif = fadd2(bif0, bif1);
                u64 ago = fadd2(bgo0, bgo1);
                float zi, zf, zg, zo;
                unpack2(aif, zi, zf);
                unpack2(ago, zg, zo);
                float iv = fmaf(0.5f, tanhf_a(zi), 0.5f);
                float fv = fmaf(0.5f, tanhf_a(zf), 0.5f);
                float gv = tanhf_a(zg);
                float ov = fmaf(0.5f, tanhf_a(zo), 0.5f);
                c2[s] = fmaf(fv, c2[s], iv * gv);
                float h2 = ov * tanhf_a(c2[s]);
                // head: butterfly reduce within the 8-lane batch group
                float p = wlu * h2;
                p += __shfl_xor_sync(FULL, p, 1);
                p += __shfl_xor_sync(FULL, p, 2);
                p += __shfl_xor_sync(FULL, p, 4);
                if (u == s8) pbuf[s] = p + blv;      // bank step t in lane t&7
                // redistribute h2 via shfl
#pragma unroll
                for (int k = 0; k < 8; k++)
                    h2x[s][k] = dup2(__shfl_sync(FULL, h2, base + k));
            }
        }

#pragma unroll
        for (int s = 0; s < 2; s++) {
            ob[s][c * CH + u] = pbuf[s];             // 8 banked steps -> coalesced
            xcur[s] = xnext[s];
        }
    }
}

extern "C" void kernel_launch(void* const* d_in, const int* in_sizes, int n_in,
                              void* d_out, int out_size)
{
    const float* x    = (const float*)d_in[0];
    const float* Wih0 = (const float*)d_in[1];
    const float* Whh0 = (const float*)d_in[2];
    const float* bih0 = (const float*)d_in[3];
    const float* bhh0 = (const float*)d_in[4];
    const float* Wih1 = (const float*)d_in[5];
    const float* Whh1 = (const float*)d_in[6];
    const float* bih1 = (const float*)d_in[7];
    const float* bhh1 = (const float*)d_in[8];
    const float* Wlin = (const float*)d_in[9];
    const float* blin = (const float*)d_in[10];
    float* out = (float*)d_out;

    // 8 batches per warp (2 streams x 4); 256 warps; 64-thread blocks ->
    // 2 warps/block on SMSP 0,1; 128 blocks spread over 128 SMs.
    const int threads = 64;
    const int blocks  = B / 16;                   // 128
    lstm2_kernel<<<blocks, threads>>>(x, Wih0, Whh0, bih0, bhh0,
                                      Wih1, Whh1, bih1, bhh1, Wlin, blin, out);
}

// round 14
// speedup vs baseline: 1.5300x; 1.5300x over previous
#include <cuda_runtime.h>

#define FULL 0xFFFFFFFFu
typedef unsigned long long u64;

constexpr int B = 2048;
constexpr int T = 4096;
constexpr int CH = 8;              // steps per chunk (= pipeline lag)
constexpr int NCHUNK = T / CH;     // 512

__device__ __forceinline__ float tanhf_a(float x){ float y; asm("tanh.approx.f32 %0,%1;":"=f"(y):"f"(x)); return y; }
__device__ __forceinline__ u64 ffma2(u64 a, u64 b, u64 c){
    u64 d; asm("fma.rn.f32x2 %0,%1,%2,%3;" : "=l"(d) : "l"(a), "l"(b), "l"(c)); return d;
}
__device__ __forceinline__ u64 fmul2(u64 a, u64 b){
    u64 d; asm("mul.rn.f32x2 %0,%1,%2;" : "=l"(d) : "l"(a), "l"(b)); return d;
}
__device__ __forceinline__ u64 fadd2(u64 a, u64 b){
    u64 d; asm("add.rn.f32x2 %0,%1,%2;" : "=l"(d) : "l"(a), "l"(b)); return d;
}
__device__ __forceinline__ u64 pack2(float lo, float hi){
    u64 d; asm("mov.b64 %0,{%1,%2};" : "=l"(d) : "f"(lo), "f"(hi)); return d;
}
__device__ __forceinline__ void unpack2(u64 v, float& lo, float& hi){
    asm("mov.b64 {%0,%1},%2;" : "=f"(lo), "=f"(hi) : "l"(v));
}
__device__ __forceinline__ u64 dup2(float v){ return pack2(v, v); }

// ONE warp, 4 batches, TWO independent chains via temporal pipelining:
//   chain A: layer-0 recurrence at time t, plus the L1-input partial
//            (b1 + Wih1*h1[t]) -> 8-step REGISTER ring (per-lane handoff,
//            no smem / barriers / syncwarp);
//   chain B: layer-1 recurrence + head at time t-8, seeded from the ring.
// The chains have no dependencies inside a chunk window, so ptxas
// interleaves them (R13 demonstrated ~100% issue for this pattern) while
// 512 warps cover 86% of SMSPs (R13's limiter was 256 warps).
// lane = (group = lane>>3, unit u = lane&7); lane computes all 4 gates of
// its unit, pair-packed (i,f),(g,o) in f32x2.
// Activations via MUFU.TANH: sigmoid(z)=0.5*tanh(0.5z)+0.5, 0.5 pre-folded.
__global__ void __launch_bounds__(128, 1)
lstm2_kernel(const float* __restrict__ x,
             const float* __restrict__ Wih0, const float* __restrict__ Whh0,
             const float* __restrict__ bih0, const float* __restrict__ bhh0,
             const float* __restrict__ Wih1, const float* __restrict__ Whh1,
             const float* __restrict__ bih1, const float* __restrict__ bhh1,
             const float* __restrict__ Wlin, const float* __restrict__ blin,
             float* __restrict__ out)
{
    const int lane  = threadIdx.x & 31;
    const int gwarp = blockIdx.x * 4 + (threadIdx.x >> 5);  // 0..511
    const int u     = lane & 7;
    const int grp   = lane >> 3;
    const int base  = lane & 24;
    const int b     = gwarp * 4 + grp;                      // this lane's batch

    const float Hs = 0.5f;

    // ---- weights: pre-scaled by activation constant, pair-packed ----
    u64 whh0_if[8], whh0_go[8], wih1_if[8], wih1_go[8], whh1_if[8], whh1_go[8];
#pragma unroll
    for (int k = 0; k < 8; k++) {
        whh0_if[k] = pack2(Hs*Whh0[u*8+k],      Hs*Whh0[(8+u)*8+k]);
        whh0_go[k] = pack2(Whh0[(16+u)*8+k],    Hs*Whh0[(24+u)*8+k]);
        wih1_if[k] = pack2(Hs*Wih1[u*8+k],      Hs*Wih1[(8+u)*8+k]);
        wih1_go[k] = pack2(Wih1[(16+u)*8+k],    Hs*Wih1[(24+u)*8+k]);
        whh1_if[k] = pack2(Hs*Whh1[u*8+k],      Hs*Whh1[(8+u)*8+k]);
        whh1_go[k] = pack2(Whh1[(16+u)*8+k],    Hs*Whh1[(24+u)*8+k]);
    }
    const u64 wx_if0 = pack2(Hs*Wih0[u],    Hs*Wih0[8+u]);
    const u64 wx_go0 = pack2(Wih0[16+u],    Hs*Wih0[24+u]);
    const u64 b_if0  = pack2(Hs*(bih0[u]+bhh0[u]),      Hs*(bih0[8+u]+bhh0[8+u]));
    const u64 b_go0  = pack2((bih0[16+u]+bhh0[16+u]),   Hs*(bih0[24+u]+bhh0[24+u]));
    const u64 b_if1  = pack2(Hs*(bih1[u]+bhh1[u]),      Hs*(bih1[8+u]+bhh1[8+u]));
    const u64 b_go1  = pack2((bih1[16+u]+bhh1[16+u]),   Hs*(bih1[24+u]+bhh1[24+u]));
    const float wlu = Wlin[u];
    const float blv = blin[0];

    // ---- state ----
    u64 h1x[8], h2x[8];
#pragma unroll
    for (int k = 0; k < 8; k++) { h1x[k] = 0ull; h2x[k] = 0ull; }
    float c1 = 0.f, c2 = 0.f, pbuf = 0.f;

    // 8-step register ring: L1-input partials (per-lane produce & consume)
    u64 bufIF[CH], bufGO[CH];

    const float* xrow = x + (size_t)b * T + u;   // lane holds x[b][c*CH + u]
    float*       ob   = out + (size_t)b * T;
    float xcur = xrow[0], xnext;

    // Chain A step: x[t] + h1x -> h1x, c1; emits L1-input partial.
    auto L0step = [&](float xt, u64& rifO, u64& rgoO) {
        u64 xd   = dup2(xt);
        u64 aif0 = ffma2(wx_if0, xd, b_if0);
        u64 ago0 = ffma2(wx_go0, xd, b_go0);
        u64 aif1 = fmul2(whh0_if[4], h1x[4]);
        u64 ago1 = fmul2(whh0_go[4], h1x[4]);
#pragma unroll
        for (int k = 0; k < 4; k++) {
            aif0 = ffma2(whh0_if[k], h1x[k], aif0);
            ago0 = ffma2(whh0_go[k], h1x[k], ago0);
        }
#pragma unroll
        for (int k = 5; k < 8; k++) {
            aif1 = ffma2(whh0_if[k], h1x[k], aif1);
            ago1 = ffma2(whh0_go[k], h1x[k], ago1);
        }
        u64 aif = fadd2(aif0, aif1);
        u64 ago = fadd2(ago0, ago1);
        float zi, zf, zg, zo;
        unpack2(aif, zi, zf);
        unpack2(ago, zg, zo);
        float iv = fmaf(0.5f, tanhf_a(zi), 0.5f);
        float fv = fmaf(0.5f, tanhf_a(zf), 0.5f);
        float gv = tanhf_a(zg);
        float ov = fmaf(0.5f, tanhf_a(zo), 0.5f);
        c1 = fmaf(fv, c1, iv * gv);
        float h = ov * tanhf_a(c1);
#pragma unroll
        for (int k = 0; k < 8; k++)
            h1x[k] = dup2(__shfl_sync(FULL, h, base + k));
        // L1-input partial (off the recurrence chain, 4+4 split)
        u64 rif0 = ffma2(wih1_if[0], h1x[0], b_if1);
        u64 rgo0 = ffma2(wih1_go[0], h1x[0], b_go1);
        u64 rif1 = fmul2(wih1_if[4], h1x[4]);
        u64 rgo1 = fmul2(wih1_go[4], h1x[4]);
#pragma unroll
        for (int k = 1; k < 4; k++) {
            rif0 = ffma2(wih1_if[k], h1x[k], rif0);
            rgo0 = ffma2(wih1_go[k], h1x[k], rgo0);
        }
#pragma unroll
        for (int k = 5; k < 8; k++) {
            rif1 = ffma2(wih1_if[k], h1x[k], rif1);
            rgo1 = ffma2(wih1_go[k], h1x[k], rgo1);
        }
        rifO = fadd2(rif0, rif1);
        rgoO = fadd2(rgo0, rgo1);
    };

    // Chain B step: ring partial + h2x -> h2x, c2; head banked in pbuf.
    auto L1step = [&](u64 pif, u64 pgo, int s8) {
        u64 bif0 = ffma2(whh1_if[0], h2x[0], pif);
        u64 bgo0 = ffma2(whh1_go[0], h2x[0], pgo);
        u64 bif1 = fmul2(whh1_if[4], h2x[4]);
        u64 bgo1 = fmul2(whh1_go[4], h2x[4]);
#pragma unroll
        for (int k = 1; k < 4; k++) {
            bif0 = ffma2(whh1_if[k], h2x[k], bif0);
            bgo0 = ffma2(whh1_go[k], h2x[k], bgo0);
        }
#pragma unroll
        for (int k = 5; k < 8; k++) {
            bif1 = ffma2(whh1_if[k], h2x[k], bif1);
            bgo1 = ffma2(whh1_go[k], h2x[k], bgo1);
        }
        u64 aif = fadd2(bif0, bif1);
        u64 ago = fadd2(bgo0, bgo1);
        float zi, zf, zg, zo;
        unpack2(aif, zi, zf);
        unpack2(ago, zg, zo);
        float iv = fmaf(0.5f, tanhf_a(zi), 0.5f);
        float fv = fmaf(0.5f, tanhf_a(zf), 0.5f);
        float gv = tanhf_a(zg);
        float ov = fmaf(0.5f, tanhf_a(zo), 0.5f);
        c2 = fmaf(fv, c2, iv * gv);
        float h2 = ov * tanhf_a(c2);
        // head: butterfly reduce within the 8-lane batch group
        float p = wlu * h2;
        p += __shfl_xor_sync(FULL, p, 1);
        p += __shfl_xor_sync(FULL, p, 2);
        p += __shfl_xor_sync(FULL, p, 4);
        if (u == s8) pbuf = p + blv;             // bank step t in lane t&7
        // redistribute h2 via shfl
#pragma unroll
        for (int k = 0; k < 8; k++)
            h2x[k] = dup2(__shfl_sync(FULL, h2, base + k));
    };

    // ---- prologue: chunk 0, chain A only (fills the ring) ----
    xnext = xrow[CH];
#pragma unroll
    for (int s = 0; s < CH; s++) {
        float xt = __shfl_sync(FULL, xcur, base + s);
        L0step(xt, bufIF[s], bufGO[s]);
    }
    xcur = xnext;

    // ---- main loop: A on chunk c, B on chunk c-1 ----
    for (int c = 1; c < NCHUNK; c++) {
        xnext = (c + 1 < NCHUNK) ? xrow[(c + 1) * CH] : 0.f;
#pragma unroll
        for (int s = 0; s < CH; s++) {
            const u64 pif = bufIF[s], pgo = bufGO[s];     // chunk c-1 partial
            float xt = __shfl_sync(FULL, xcur, base + s);
            L0step(xt, bufIF[s], bufGO[s]);               // chain A (chunk c)
            L1step(pif, pgo, s);                          // chain B (chunk c-1)
        }
        ob[(c - 1) * CH + u] = pbuf;                      // coalesced, 8 steps
        xcur = xnext;
    }

    // ---- epilogue: chain B on the final chunk ----
#pragma unroll
    for (int s = 0; s < CH; s++)
        L1step(bufIF[s], bufGO[s], s);
    ob[(NCHUNK - 1) * CH + u] = pbuf;
}

extern "C" void kernel_launch(void* const* d_in, const int* in_sizes, int n_in,
                              void* d_out, int out_size)
{
    const float* x    = (const float*)d_in[0];
    const float* Wih0 = (const float*)d_in[1];
    const float* Whh0 = (const float*)d_in[2];
    const float* bih0 = (const float*)d_in[3];
    const float* bhh0 = (const float*)d_in[4];
    const float* Wih1 = (const float*)d_in[5];
    const float* Whh1 = (const float*)d_in[6];
    const float* bih1 = (const float*)d_in[7];
    const float* bhh1 = (const float*)d_in[8];
    const float* Wlin = (const float*)d_in[9];
    const float* blin = (const float*)d_in[10];
    float* out = (float*)d_out;

    // 4 batches per warp; 512 warps; 128-thread blocks -> warps 0-3 land on
    // SMSPs 0-3, 128 blocks over 128 SMs = 1 warp per SMSP on 86% of chip.
    const int threads = 128;
    const int blocks  = B / 16;                   // 128
    lstm2_kernel<<<blocks, threads>>>(x, Wih0, Whh0, bih0, bhh0,
                                      Wih1, Whh1, bih1, bhh1, Wlin, blin, out);
}

// round 15
// speedup vs baseline: 1.6967x; 1.1089x over previous
#include <cuda_runtime.h>

#define FULL 0xFFFFFFFFu
typedef unsigned long long u64;

constexpr int B = 2048;
constexpr int T = 4096;
constexpr int CH = 8;              // steps per chunk (= pipeline lag)
constexpr int NCHUNK = T / CH;     // 512

__device__ __forceinline__ float tanhf_a(float x){ float y; asm("tanh.approx.f32 %0,%1;":"=f"(y):"f"(x)); return y; }
__device__ __forceinline__ u64 ffma2(u64 a, u64 b, u64 c){
    u64 d; asm("fma.rn.f32x2 %0,%1,%2,%3;" : "=l"(d) : "l"(a), "l"(b), "l"(c)); return d;
}
__device__ __forceinline__ u64 fmul2(u64 a, u64 b){
    u64 d; asm("mul.rn.f32x2 %0,%1,%2;" : "=l"(d) : "l"(a), "l"(b)); return d;
}
__device__ __forceinline__ u64 fadd2(u64 a, u64 b){
    u64 d; asm("add.rn.f32x2 %0,%1,%2;" : "=l"(d) : "l"(a), "l"(b)); return d;
}
__device__ __forceinline__ u64 pack2(float lo, float hi){
    u64 d; asm("mov.b64 %0,{%1,%2};" : "=l"(d) : "f"(lo), "f"(hi)); return d;
}
__device__ __forceinline__ void unpack2(u64 v, float& lo, float& hi){
    asm("mov.b64 {%0,%1},%2;" : "=f"(lo), "=f"(hi) : "l"(v));
}
__device__ __forceinline__ u64 dup2(float v){ return pack2(v, v); }

// ONE warp, 4 batches, TWO independent chains via temporal pipelining:
//   chain A: layer-0 recurrence at time t + L1-input partial -> register ring
//   chain B: layer-1 recurrence + head at time t-8, seeded from the ring.
// R15: the two chains are STATEMENT-LEVEL INTERLEAVED in one basic block
// (R13 proved ptxas interleaves only what is adjacent in source; R14's
// sequential L0step();L1step() calls serialized the chains).
// lane = (group = lane>>3, unit u = lane&7); lane computes all 4 gates of
// its unit, pair-packed (i,f),(g,o) in f32x2.
// Activations via MUFU.TANH: sigmoid(z)=0.5*tanh(0.5z)+0.5, 0.5 pre-folded.
__global__ void __launch_bounds__(128, 1)
lstm2_kernel(const float* __restrict__ x,
             const float* __restrict__ Wih0, const float* __restrict__ Whh0,
             const float* __restrict__ bih0, const float* __restrict__ bhh0,
             const float* __restrict__ Wih1, const float* __restrict__ Whh1,
             const float* __restrict__ bih1, const float* __restrict__ bhh1,
             const float* __restrict__ Wlin, const float* __restrict__ blin,
             float* __restrict__ out)
{
    const int lane  = threadIdx.x & 31;
    const int gwarp = blockIdx.x * 4 + (threadIdx.x >> 5);  // 0..511
    const int u     = lane & 7;
    const int grp   = lane >> 3;
    const int base  = lane & 24;
    const int b     = gwarp * 4 + grp;                      // this lane's batch

    const float Hs = 0.5f;

    // ---- weights: pre-scaled by activation constant, pair-packed ----
    u64 whh0_if[8], whh0_go[8], wih1_if[8], wih1_go[8], whh1_if[8], whh1_go[8];
#pragma unroll
    for (int k = 0; k < 8; k++) {
        whh0_if[k] = pack2(Hs*Whh0[u*8+k],      Hs*Whh0[(8+u)*8+k]);
        whh0_go[k] = pack2(Whh0[(16+u)*8+k],    Hs*Whh0[(24+u)*8+k]);
        wih1_if[k] = pack2(Hs*Wih1[u*8+k],      Hs*Wih1[(8+u)*8+k]);
        wih1_go[k] = pack2(Wih1[(16+u)*8+k],    Hs*Wih1[(24+u)*8+k]);
        whh1_if[k] = pack2(Hs*Whh1[u*8+k],      Hs*Whh1[(8+u)*8+k]);
        whh1_go[k] = pack2(Whh1[(16+u)*8+k],    Hs*Whh1[(24+u)*8+k]);
    }
    const u64 wx_if0 = pack2(Hs*Wih0[u],    Hs*Wih0[8+u]);
    const u64 wx_go0 = pack2(Wih0[16+u],    Hs*Wih0[24+u]);
    const u64 b_if0  = pack2(Hs*(bih0[u]+bhh0[u]),      Hs*(bih0[8+u]+bhh0[8+u]));
    const u64 b_go0  = pack2((bih0[16+u]+bhh0[16+u]),   Hs*(bih0[24+u]+bhh0[24+u]));
    const u64 b_if1  = pack2(Hs*(bih1[u]+bhh1[u]),      Hs*(bih1[8+u]+bhh1[8+u]));
    const u64 b_go1  = pack2((bih1[16+u]+bhh1[16+u]),   Hs*(bih1[24+u]+bhh1[24+u]));
    const float wlu = Wlin[u];
    const float blv = blin[0];

    // ---- state ----
    u64 h1x[8], h2x[8];
#pragma unroll
    for (int k = 0; k < 8; k++) { h1x[k] = 0ull; h2x[k] = 0ull; }
    float c1 = 0.f, c2 = 0.f, pbuf = 0.f;

    // 8-step register ring: L1-input partials (per-lane produce & consume)
    u64 bufIF[CH], bufGO[CH];

    const float* xrow = x + (size_t)b * T + u;   // lane holds x[b][c*CH + u]
    float*       ob   = out + (size_t)b * T;
    float xcur = xrow[0], xnext;

    // emit the L1-input partial for the CURRENT h1x (off-chain filler FMAs)
    auto emit_partial = [&](u64& rifO, u64& rgoO) {
        u64 rif0 = ffma2(wih1_if[0], h1x[0], b_if1);
        u64 rgo0 = ffma2(wih1_go[0], h1x[0], b_go1);
        u64 rif1 = fmul2(wih1_if[4], h1x[4]);
        u64 rgo1 = fmul2(wih1_go[4], h1x[4]);
#pragma unroll
        for (int k = 1; k < 4; k++) {
            rif0 = ffma2(wih1_if[k], h1x[k], rif0);
            rgo0 = ffma2(wih1_go[k], h1x[k], rgo0);
        }
#pragma unroll
        for (int k = 5; k < 8; k++) {
            rif1 = ffma2(wih1_if[k], h1x[k], rif1);
            rgo1 = ffma2(wih1_go[k], h1x[k], rgo1);
        }
        rifO = fadd2(rif0, rif1);
        rgoO = fadd2(rgo0, rgo1);
    };

    // Chain-A-only step (prologue)
    auto L0only = [&](float xt, u64& rifO, u64& rgoO) {
        u64 xd   = dup2(xt);
        u64 aif0 = ffma2(wx_if0, xd, b_if0);
        u64 ago0 = ffma2(wx_go0, xd, b_go0);
        u64 aif1 = fmul2(whh0_if[4], h1x[4]);
        u64 ago1 = fmul2(whh0_go[4], h1x[4]);
#pragma unroll
        for (int k = 0; k < 4; k++) {
            aif0 = ffma2(whh0_if[k], h1x[k], aif0);
            ago0 = ffma2(whh0_go[k], h1x[k], ago0);
        }
#pragma unroll
        for (int k = 5; k < 8; k++) {
            aif1 = ffma2(whh0_if[k], h1x[k], aif1);
            ago1 = ffma2(whh0_go[k], h1x[k], ago1);
        }
        u64 aif = fadd2(aif0, aif1);
        u64 ago = fadd2(ago0, ago1);
        float zi, zf, zg, zo;
        unpack2(aif, zi, zf);
        unpack2(ago, zg, zo);
        float iv = fmaf(0.5f, tanhf_a(zi), 0.5f);
        float fv = fmaf(0.5f, tanhf_a(zf), 0.5f);
        float gv = tanhf_a(zg);
        float ov = fmaf(0.5f, tanhf_a(zo), 0.5f);
        c1 = fmaf(fv, c1, iv * gv);
        float h = ov * tanhf_a(c1);
#pragma unroll
        for (int k = 0; k < 8; k++)
            h1x[k] = dup2(__shfl_sync(FULL, h, base + k));
        emit_partial(rifO, rgoO);
    };

    // Chain-B-only step (epilogue)
    auto L1only = [&](u64 pif, u64 pgo, int s8) {
        u64 bif0 = ffma2(whh1_if[0], h2x[0], pif);
        u64 bgo0 = ffma2(whh1_go[0], h2x[0], pgo);
        u64 bif1 = fmul2(whh1_if[4], h2x[4]);
        u64 bgo1 = fmul2(whh1_go[4], h2x[4]);
#pragma unroll
        for (int k = 1; k < 4; k++) {
            bif0 = ffma2(whh1_if[k], h2x[k], bif0);
            bgo0 = ffma2(whh1_go[k], h2x[k], bgo0);
        }
#pragma unroll
        for (int k = 5; k < 8; k++) {
            bif1 = ffma2(whh1_if[k], h2x[k], bif1);
            bgo1 = ffma2(whh1_go[k], h2x[k], bgo1);
        }
        u64 aif = fadd2(bif0, bif1);
        u64 ago = fadd2(bgo0, bgo1);
        float zi, zf, zg, zo;
        unpack2(aif, zi, zf);
        unpack2(ago, zg, zo);
        float iv = fmaf(0.5f, tanhf_a(zi), 0.5f);
        float fv = fmaf(0.5f, tanhf_a(zf), 0.5f);
        float gv = tanhf_a(zg);
        float ov = fmaf(0.5f, tanhf_a(zo), 0.5f);
        c2 = fmaf(fv, c2, iv * gv);
        float h2 = ov * tanhf_a(c2);
        float p = wlu * h2;
        p += __shfl_xor_sync(FULL, p, 1);
        p += __shfl_xor_sync(FULL, p, 2);
        p += __shfl_xor_sync(FULL, p, 4);
        if (u == s8) pbuf = p + blv;
#pragma unroll
        for (int k = 0; k < 8; k++)
            h2x[k] = dup2(__shfl_sync(FULL, h2, base + k));
    };

    // ---- prologue: chunk 0, chain A only (fills the ring) ----
    xnext = xrow[CH];
#pragma unroll
    for (int s = 0; s < CH; s++) {
        float xt = __shfl_sync(FULL, xcur, base + s);
        L0only(xt, bufIF[s], bufGO[s]);
    }
    xcur = xnext;

    // ---- main loop: A on chunk c, B on chunk c-1, statement-interleaved ----
    for (int c = 1; c < NCHUNK; c++) {
        xnext = (c + 1 < NCHUNK) ? xrow[(c + 1) * CH] : 0.f;
#pragma unroll
        for (int s = 0; s < CH; s++) {
            const u64 pif = bufIF[s], pgo = bufGO[s];     // chunk c-1 partial
            float xt = __shfl_sync(FULL, xcur, base + s);
            u64 xd = dup2(xt);

            // ===== interleaved matvecs: A (L0 @ t) & B (L1 @ t-8) =====
            u64 Aif0 = ffma2(wx_if0, xd, b_if0);
            u64 Ago0 = ffma2(wx_go0, xd, b_go0);
            u64 Bif0 = ffma2(whh1_if[0], h2x[0], pif);
            u64 Bgo0 = ffma2(whh1_go[0], h2x[0], pgo);
            u64 Aif1 = fmul2(whh0_if[4], h1x[4]);
            u64 Ago1 = fmul2(whh0_go[4], h1x[4]);
            u64 Bif1 = fmul2(whh1_if[4], h2x[4]);
            u64 Bgo1 = fmul2(whh1_go[4], h2x[4]);
#pragma unroll
            for (int k = 1; k < 4; k++) {
                Aif0 = ffma2(whh0_if[k], h1x[k], Aif0);
                Bif0 = ffma2(whh1_if[k], h2x[k], Bif0);
                Ago0 = ffma2(whh0_go[k], h1x[k], Ago0);
                Bgo0 = ffma2(whh1_go[k], h2x[k], Bgo0);
            }
            Aif0 = ffma2(whh0_if[0], h1x[0], Aif0);      // A's k=0 (B seeded k=0)
            Ago0 = ffma2(whh0_go[0], h1x[0], Ago0);
#pragma unroll
            for (int k = 5; k < 8; k++) {
                Aif1 = ffma2(whh0_if[k], h1x[k], Aif1);
                Bif1 = ffma2(whh1_if[k], h2x[k], Bif1);
                Ago1 = ffma2(whh0_go[k], h1x[k], Ago1);
                Bgo1 = ffma2(whh1_go[k], h2x[k], Bgo1);
            }
            u64 Aif = fadd2(Aif0, Aif1), Ago = fadd2(Ago0, Ago1);
            u64 Bif = fadd2(Bif0, Bif1), Bgo = fadd2(Bgo0, Bgo1);

            // ===== interleaved activations (8 MUFU back-to-back) =====
            float Azi, Azf, Azg, Azo, Bzi, Bzf, Bzg, Bzo;
            unpack2(Aif, Azi, Azf);
            unpack2(Bif, Bzi, Bzf);
            unpack2(Ago, Azg, Azo);
            unpack2(Bgo, Bzg, Bzo);
            float Aiv = fmaf(0.5f, tanhf_a(Azi), 0.5f);
            float Biv = fmaf(0.5f, tanhf_a(Bzi), 0.5f);
            float Afv = fmaf(0.5f, tanhf_a(Azf), 0.5f);
            float Bfv = fmaf(0.5f, tanhf_a(Bzf), 0.5f);
            float Agv = tanhf_a(Azg);
            float Bgv = tanhf_a(Bzg);
            float Aov = fmaf(0.5f, tanhf_a(Azo), 0.5f);
            float Bov = fmaf(0.5f, tanhf_a(Bzo), 0.5f);

            // ===== interleaved cell updates =====
            c1 = fmaf(Afv, c1, Aiv * Agv);
            c2 = fmaf(Bfv, c2, Biv * Bgv);
            float Ah = Aov * tanhf_a(c1);
            float Bh = Bov * tanhf_a(c2);

            // ===== interleaved epilogues: A h1-redist | B head + h2-redist =====
            float p = wlu * Bh;
            p += __shfl_xor_sync(FULL, p, 1);
#pragma unroll
            for (int k = 0; k < 4; k++)
                h1x[k] = dup2(__shfl_sync(FULL, Ah, base + k));
            p += __shfl_xor_sync(FULL, p, 2);
#pragma unroll
            for (int k = 4; k < 8; k++)
                h1x[k] = dup2(__shfl_sync(FULL, Ah, base + k));
            p += __shfl_xor_sync(FULL, p, 4);
            if (u == s) pbuf = p + blv;               // bank step t-8 in lane
#pragma unroll
            for (int k = 0; k < 8; k++)
                h2x[k] = dup2(__shfl_sync(FULL, Bh, base + k));

            // ===== A: L1-input partial -> ring (off-chain filler) =====
            emit_partial(bufIF[s], bufGO[s]);
        }
        ob[(c - 1) * CH + u] = pbuf;                  // coalesced, 8 steps
        xcur = xnext;
    }

    // ---- epilogue: chain B on the final chunk ----
#pragma unroll
    for (int s = 0; s < CH; s++)
        L1only(bufIF[s], bufGO[s], s);
    ob[(NCHUNK - 1) * CH + u] = pbuf;
}

extern "C" void kernel_launch(void* const* d_in, const int* in_sizes, int n_in,
                              void* d_out, int out_size)
{
    const float* x    = (const float*)d_in[0];
    const float* Wih0 = (const float*)d_in[1];
    const float* Whh0 = (const float*)d_in[2];
    const float* bih0 = (const float*)d_in[3];
    const float* bhh0 = (const float*)d_in[4];
    const float* Wih1 = (const float*)d_in[5];
    const float* Whh1 = (const float*)d_in[6];
    const float* bih1 = (const float*)d_in[7];
    const float* bhh1 = (const float*)d_in[8];
    const float* Wlin = (const float*)d_in[9];
    const float* blin = (const float*)d_in[10];
    float* out = (float*)d_out;

    // 4 batches per warp; 512 warps; 128-thread blocks -> warps 0-3 land on
    // SMSPs 0-3, 128 blocks over 128 SMs = 1 warp per SMSP on 86% of chip.
    const int threads = 128;
    const int blocks  = B / 16;                   // 128
    lstm2_kernel<<<blocks, threads>>>(x, Wih0, Whh0, bih0, bhh0,
                                      Wih1, Whh1, bih1, bhh1, Wlin, blin, out);
}